// round 1
// baseline (speedup 1.0000x reference)
#include <cuda_runtime.h>

#define N 512
#define D 256

// Scratch (device globals — no allocation allowed in kernel_launch)
__device__ float g_q[N * N];
__device__ float g_k[N * N];
__device__ float g_v[N * N];
__device__ float g_s[N * N];

// ---------------------------------------------------------------------------
// Kernel 1: fused rank-1 projections. q = x_q @ WQ, k = x_k @ WK, v = x_v @ WV
// One warp per 256-element row; float4 loads; warp shuffle reduce.
// Total traffic: 3 * 512*512*256 * 4B = 768 MB reads (HBM-bound).
// ---------------------------------------------------------------------------
__global__ void __launch_bounds__(256) proj_kernel(
    const float* __restrict__ xq, const float* __restrict__ xk,
    const float* __restrict__ xv, const float* __restrict__ WQ,
    const float* __restrict__ WK, const float* __restrict__ WV)
{
    __shared__ float sW[3][D];
    int tid = threadIdx.x;
    // 256 threads load the three D=256 weight vectors
    sW[0][tid] = WQ[tid];
    sW[1][tid] = WK[tid];
    sW[2][tid] = WV[tid];
    __syncthreads();

    int warp = tid >> 5;
    int lane = tid & 31;
    long long row = (long long)blockIdx.x * 8 + warp;   // 8 warps per block
    if (row >= 3LL * N * N) return;

    int t = (int)(row / (N * N));       // 0=q, 1=k, 2=v
    int r = (int)(row % (N * N));

    const float* x = (t == 0) ? xq : (t == 1) ? xk : xv;
    const float4* xr = reinterpret_cast<const float4*>(x + (size_t)r * D);
    const float4* w4 = reinterpret_cast<const float4*>(sW[t]);

    float acc = 0.0f;
#pragma unroll
    for (int i = 0; i < 2; i++) {
        float4 a = xr[lane + i * 32];
        float4 b = w4[lane + i * 32];
        acc += a.x * b.x + a.y * b.y + a.z * b.z + a.w * b.w;
    }
#pragma unroll
    for (int o = 16; o > 0; o >>= 1)
        acc += __shfl_xor_sync(0xffffffffu, acc, o);

    if (lane == 0) {
        float* g = (t == 0) ? g_q : (t == 1) ? g_k : g_v;
        g[r] = acc;
    }
}

// ---------------------------------------------------------------------------
// Kernel 2/4: C = A @ B, all 512x512 fp32. 64x64 block tile, BK=16,
// 256 threads, 4x4 microtile per thread.
// mode 0: g_s = g_q @ g_k ;  mode 1: out = g_s @ g_v
// ---------------------------------------------------------------------------
__global__ void __launch_bounds__(256) sgemm_kernel(int mode, float* __restrict__ out)
{
    const float* __restrict__ A = (mode == 0) ? g_q : g_s;
    const float* __restrict__ B = (mode == 0) ? g_k : g_v;
    float* __restrict__ C = (mode == 0) ? g_s : out;

    __shared__ float As[16][64];
    __shared__ float Bs[16][64];

    int bx = blockIdx.x * 64;
    int by = blockIdx.y * 64;
    int tid = threadIdx.x;         // 0..255
    int tx = tid % 16;             // N-tile position
    int ty = tid / 16;             // M-tile position

    float acc[4][4] = {};

    for (int k0 = 0; k0 < N; k0 += 16) {
        // Load A tile [64 x 16] -> As[k][m]
#pragma unroll
        for (int i = tid; i < 1024; i += 256) {
            int m = i >> 4, kk = i & 15;
            As[kk][m] = A[(by + m) * N + k0 + kk];
        }
        // Load B tile [16 x 64] -> Bs[k][n]
#pragma unroll
        for (int i = tid; i < 1024; i += 256) {
            int kk = i >> 6, n = i & 63;
            Bs[kk][n] = B[(k0 + kk) * N + bx + n];
        }
        __syncthreads();

#pragma unroll
        for (int kk = 0; kk < 16; kk++) {
            float a[4], b[4];
#pragma unroll
            for (int i = 0; i < 4; i++) a[i] = As[kk][ty * 4 + i];
#pragma unroll
            for (int j = 0; j < 4; j++) b[j] = Bs[kk][tx * 4 + j];
#pragma unroll
            for (int i = 0; i < 4; i++)
#pragma unroll
                for (int j = 0; j < 4; j++)
                    acc[i][j] += a[i] * b[j];
        }
        __syncthreads();
    }

#pragma unroll
    for (int i = 0; i < 4; i++)
#pragma unroll
        for (int j = 0; j < 4; j++)
            C[(by + ty * 4 + i) * N + bx + tx * 4 + j] = acc[i][j];
}

// ---------------------------------------------------------------------------
// Kernel 3: row softmax over g_s (512 rows). One block of 256 threads per row,
// 2 elements per thread.
// ---------------------------------------------------------------------------
__global__ void __launch_bounds__(256) softmax_kernel()
{
    __shared__ float red[256];
    int row = blockIdx.x;
    float* p = g_s + (size_t)row * N;
    int tid = threadIdx.x;

    float a = p[tid];
    float b = p[tid + 256];

    // max reduce
    red[tid] = fmaxf(a, b);
    __syncthreads();
#pragma unroll
    for (int o = 128; o > 0; o >>= 1) {
        if (tid < o) red[tid] = fmaxf(red[tid], red[tid + o]);
        __syncthreads();
    }
    float mx = red[0];
    __syncthreads();

    float ea = __expf(a - mx);
    float eb = __expf(b - mx);

    // sum reduce
    red[tid] = ea + eb;
    __syncthreads();
#pragma unroll
    for (int o = 128; o > 0; o >>= 1) {
        if (tid < o) red[tid] += red[tid + o];
        __syncthreads();
    }
    float inv = 1.0f / red[0];

    p[tid] = ea * inv;
    p[tid + 256] = eb * inv;
}

// ---------------------------------------------------------------------------
extern "C" void kernel_launch(void* const* d_in, const int* in_sizes, int n_in,
                              void* d_out, int out_size)
{
    const float* xq = (const float*)d_in[0];
    const float* xk = (const float*)d_in[1];
    const float* xv = (const float*)d_in[2];
    const float* WQ = (const float*)d_in[3];
    const float* WK = (const float*)d_in[4];
    const float* WV = (const float*)d_in[5];
    float* out = (float*)d_out;

    // 1) projections: 3*N*N rows, 8 warps (rows) per 256-thread block
    int total_rows = 3 * N * N;
    int blocks = (total_rows + 7) / 8;
    proj_kernel<<<blocks, 256>>>(xq, xk, xv, WQ, WK, WV);

    // 2) s = q @ k
    dim3 g2(N / 64, N / 64);
    sgemm_kernel<<<g2, 256>>>(0, out);

    // 3) softmax rows of s
    softmax_kernel<<<N, 256>>>();

    // 4) out = s @ v
    sgemm_kernel<<<g2, 256>>>(1, out);
}

// round 2
// speedup vs baseline: 1.2000x; 1.2000x over previous
#include <cuda_runtime.h>

#define N 512
#define D 256

// Scratch (device globals — no allocation allowed in kernel_launch)
__device__ float g_q[N * N];
__device__ float g_k[N * N];
__device__ float g_v[N * N];
__device__ float g_s[N * N];

// ---------------------------------------------------------------------------
// Kernel 1: fused rank-1 projections. q = x_q @ WQ, k = x_k @ WK, v = x_v @ WV
// One warp per 256-element row; float4 loads; warp shuffle reduce.
// 768 MB of reads -> HBM-bound, near floor.
// ---------------------------------------------------------------------------
__global__ void __launch_bounds__(256) proj_kernel(
    const float* __restrict__ xq, const float* __restrict__ xk,
    const float* __restrict__ xv, const float* __restrict__ WQ,
    const float* __restrict__ WK, const float* __restrict__ WV)
{
    __shared__ float sW[3][D];
    int tid = threadIdx.x;
    sW[0][tid] = WQ[tid];
    sW[1][tid] = WK[tid];
    sW[2][tid] = WV[tid];
    __syncthreads();

    int warp = tid >> 5;
    int lane = tid & 31;
    long long row = (long long)blockIdx.x * 8 + warp;   // 8 warps per block
    if (row >= 3LL * N * N) return;

    int t = (int)(row / (N * N));       // 0=q, 1=k, 2=v
    int r = (int)(row % (N * N));

    const float* x = (t == 0) ? xq : (t == 1) ? xk : xv;
    const float4* xr = reinterpret_cast<const float4*>(x + (size_t)r * D);
    const float4* w4 = reinterpret_cast<const float4*>(sW[t]);

    float acc = 0.0f;
#pragma unroll
    for (int i = 0; i < 2; i++) {
        float4 a = xr[lane + i * 32];
        float4 b = w4[lane + i * 32];
        acc += a.x * b.x + a.y * b.y + a.z * b.z + a.w * b.w;
    }
#pragma unroll
    for (int o = 16; o > 0; o >>= 1)
        acc += __shfl_xor_sync(0xffffffffu, acc, o);

    if (lane == 0) {
        float* g = (t == 0) ? g_q : (t == 1) ? g_k : g_v;
        g[r] = acc;
    }
}

// ---------------------------------------------------------------------------
// Kernel 2/4: C = A @ B, 512x512x512 fp32.
// Tile: BM=32, BN=64, BK=32. Grid = (8,16) = 128 blocks (one per SM).
// 256 threads, 2x4 microtile, register-prefetch pipeline over k0.
// mode 0: g_s = g_q @ g_k ;  mode 1: out = g_s @ g_v
// ---------------------------------------------------------------------------
__global__ void __launch_bounds__(256) sgemm_kernel(int mode, float* __restrict__ out)
{
    const float* __restrict__ A = (mode == 0) ? g_q : g_s;
    const float* __restrict__ B = (mode == 0) ? g_k : g_v;
    float* __restrict__ C = (mode == 0) ? g_s : out;

    __shared__ float As[32][34];   // [k][m], pad keeps float2 alignment, avoids conflicts
    __shared__ float Bs[32][64];   // [k][n]

    const int bx = blockIdx.x * 64;   // n offset
    const int by = blockIdx.y * 32;   // m offset
    const int tid = threadIdx.x;
    const int tx = tid & 15;          // n micro (16 * 4 = 64)
    const int ty = tid >> 4;          // m micro (16 * 2 = 32)

    // Global load assignments
    const int am = tid >> 3;          // 0..31  (A row within tile)
    const int ak = (tid & 7) * 4;     // 0..28  (A k within tile, float4)
    const int bn = (tid & 15) * 4;    // 0..60  (B n within tile, float4)
    const int bk = tid >> 4;          // 0..15  (B k within tile; +16 for 2nd)

    // Prefetch tile k0 = 0
    float4 aReg  = *(const float4*)&A[(by + am) * N + ak];
    float4 bReg0 = *(const float4*)&B[(bk)      * N + bx + bn];
    float4 bReg1 = *(const float4*)&B[(bk + 16) * N + bx + bn];

    float acc[2][4] = {};

    for (int k0 = 0; k0 < N; k0 += 32) {
        // Commit prefetched tile to smem (A transposed to [k][m])
        As[ak + 0][am] = aReg.x;
        As[ak + 1][am] = aReg.y;
        As[ak + 2][am] = aReg.z;
        As[ak + 3][am] = aReg.w;
        *(float4*)&Bs[bk][bn]      = bReg0;
        *(float4*)&Bs[bk + 16][bn] = bReg1;
        __syncthreads();

        // Prefetch next tile while computing this one
        if (k0 + 32 < N) {
            aReg  = *(const float4*)&A[(by + am) * N + k0 + 32 + ak];
            bReg0 = *(const float4*)&B[(k0 + 32 + bk) * N + bx + bn];
            bReg1 = *(const float4*)&B[(k0 + 48 + bk) * N + bx + bn];
        }

#pragma unroll
        for (int kk = 0; kk < 32; kk++) {
            float2 a = *(const float2*)&As[kk][ty * 2];
            float4 b = *(const float4*)&Bs[kk][tx * 4];
            acc[0][0] += a.x * b.x;
            acc[0][1] += a.x * b.y;
            acc[0][2] += a.x * b.z;
            acc[0][3] += a.x * b.w;
            acc[1][0] += a.y * b.x;
            acc[1][1] += a.y * b.y;
            acc[1][2] += a.y * b.z;
            acc[1][3] += a.y * b.w;
        }
        __syncthreads();
    }

#pragma unroll
    for (int i = 0; i < 2; i++) {
        float4 r = make_float4(acc[i][0], acc[i][1], acc[i][2], acc[i][3]);
        *(float4*)&C[(by + ty * 2 + i) * N + bx + tx * 4] = r;
    }
}

// ---------------------------------------------------------------------------
// Kernel 3: row softmax over g_s (512 rows). One block of 256 threads per row.
// ---------------------------------------------------------------------------
__global__ void __launch_bounds__(256) softmax_kernel()
{
    __shared__ float red[256];
    int row = blockIdx.x;
    float* p = g_s + (size_t)row * N;
    int tid = threadIdx.x;

    float a = p[tid];
    float b = p[tid + 256];

    red[tid] = fmaxf(a, b);
    __syncthreads();
#pragma unroll
    for (int o = 128; o > 0; o >>= 1) {
        if (tid < o) red[tid] = fmaxf(red[tid], red[tid + o]);
        __syncthreads();
    }
    float mx = red[0];
    __syncthreads();

    float ea = __expf(a - mx);
    float eb = __expf(b - mx);

    red[tid] = ea + eb;
    __syncthreads();
#pragma unroll
    for (int o = 128; o > 0; o >>= 1) {
        if (tid < o) red[tid] += red[tid + o];
        __syncthreads();
    }
    float inv = 1.0f / red[0];

    p[tid] = ea * inv;
    p[tid + 256] = eb * inv;
}

// ---------------------------------------------------------------------------
extern "C" void kernel_launch(void* const* d_in, const int* in_sizes, int n_in,
                              void* d_out, int out_size)
{
    const float* xq = (const float*)d_in[0];
    const float* xk = (const float*)d_in[1];
    const float* xv = (const float*)d_in[2];
    const float* WQ = (const float*)d_in[3];
    const float* WK = (const float*)d_in[4];
    const float* WV = (const float*)d_in[5];
    float* out = (float*)d_out;

    // 1) projections: 3*N*N rows, 8 warps (rows) per 256-thread block
    int total_rows = 3 * N * N;
    int blocks = (total_rows + 7) / 8;
    proj_kernel<<<blocks, 256>>>(xq, xk, xv, WQ, WK, WV);

    // 2) s = q @ k   (grid: 8 x-tiles of 64 cols, 16 y-tiles of 32 rows)
    dim3 g2(N / 64, N / 32);
    sgemm_kernel<<<g2, 256>>>(0, out);

    // 3) softmax rows of s
    softmax_kernel<<<N, 256>>>();

    // 4) out = s @ v
    sgemm_kernel<<<g2, 256>>>(1, out);
}

// round 3
// speedup vs baseline: 1.3110x; 1.0924x over previous
#include <cuda_runtime.h>

#define N 512
#define D 256
#define KSPLIT 4

// Scratch (device globals — no allocation allowed)
__device__ float g_q[N * N];
__device__ float g_k[N * N];
__device__ float g_v[N * N];
__device__ float g_s[N * N];
__device__ float g_sp[KSPLIT][N * N];   // split-K partials of q@k
__device__ float g_op[KSPLIT][N * N];   // split-K partials of s@v

// ---------------------------------------------------------------------------
// Kernel 1: fused rank-1 projections (HBM-bound, ~90% of achievable BW).
// ---------------------------------------------------------------------------
__global__ void __launch_bounds__(256) proj_kernel(
    const float* __restrict__ xq, const float* __restrict__ xk,
    const float* __restrict__ xv, const float* __restrict__ WQ,
    const float* __restrict__ WK, const float* __restrict__ WV)
{
    __shared__ float sW[3][D];
    int tid = threadIdx.x;
    sW[0][tid] = WQ[tid];
    sW[1][tid] = WK[tid];
    sW[2][tid] = WV[tid];
    __syncthreads();

    int warp = tid >> 5;
    int lane = tid & 31;
    long long row = (long long)blockIdx.x * 8 + warp;
    if (row >= 3LL * N * N) return;

    int t = (int)(row / (N * N));
    int r = (int)(row % (N * N));

    const float* x = (t == 0) ? xq : (t == 1) ? xk : xv;
    const float4* xr = reinterpret_cast<const float4*>(x + (size_t)r * D);
    const float4* w4 = reinterpret_cast<const float4*>(sW[t]);

    float acc = 0.0f;
#pragma unroll
    for (int i = 0; i < 2; i++) {
        float4 a = xr[lane + i * 32];
        float4 b = w4[lane + i * 32];
        acc += a.x * b.x + a.y * b.y + a.z * b.z + a.w * b.w;
    }
#pragma unroll
    for (int o = 16; o > 0; o >>= 1)
        acc += __shfl_xor_sync(0xffffffffu, acc, o);

    if (lane == 0) {
        float* g = (t == 0) ? g_q : (t == 1) ? g_k : g_v;
        g[r] = acc;
    }
}

// ---------------------------------------------------------------------------
// Kernel 2/4: split-K SGEMM partials. C_part[z] = A[:, zK:(z+1)K] @ B[zK:...]
// BM=64, BN=64, BK=32; 256 threads; 4x4 microtile; grid (8,8,KSPLIT).
// mode 0: A=g_q, B=g_k, C=g_sp[z];  mode 1: A=g_s, B=g_v, C=g_op[z]
// ---------------------------------------------------------------------------
__global__ void __launch_bounds__(256) sgemm_kernel(int mode)
{
    const float* __restrict__ A = (mode == 0) ? g_q : g_s;
    const float* __restrict__ B = (mode == 0) ? g_k : g_v;
    float* __restrict__ C = (mode == 0) ? g_sp[blockIdx.z] : g_op[blockIdx.z];

    __shared__ float As[32][68];   // [k][m], pad=4 keeps 16B align, spreads banks
    __shared__ float Bs[32][64];   // [k][n]

    const int bx = blockIdx.x * 64;          // n offset
    const int by = blockIdx.y * 64;          // m offset
    const int kbase = blockIdx.z * (N / KSPLIT);  // 128-wide K slice
    const int tid = threadIdx.x;
    const int tx = tid & 15;                  // n micro
    const int ty = tid >> 4;                  // m micro

    // Global load assignments
    const int am = tid >> 3;                  // 0..31 (A row; +32 for 2nd)
    const int ak = (tid & 7) * 4;             // 0..28 (A k, float4)
    const int bn = (tid & 15) * 4;            // 0..60 (B n, float4)
    const int bk = tid >> 4;                  // 0..15 (B k; +16 for 2nd)

    // Prefetch first tile
    float4 a0 = *(const float4*)&A[(by + am) * N + kbase + ak];
    float4 a1 = *(const float4*)&A[(by + am + 32) * N + kbase + ak];
    float4 b0 = *(const float4*)&B[(kbase + bk) * N + bx + bn];
    float4 b1 = *(const float4*)&B[(kbase + bk + 16) * N + bx + bn];

    float acc[4][4] = {};

    for (int k0 = 0; k0 < N / KSPLIT; k0 += 32) {
        // Commit prefetched tile (A transposed to [k][m])
#pragma unroll
        for (int j = 0; j < 4; j++) {
            As[ak + j][am]      = ((const float*)&a0)[j];
            As[ak + j][am + 32] = ((const float*)&a1)[j];
        }
        *(float4*)&Bs[bk][bn]      = b0;
        *(float4*)&Bs[bk + 16][bn] = b1;
        __syncthreads();

        // Prefetch next tile
        if (k0 + 32 < N / KSPLIT) {
            int kn = kbase + k0 + 32;
            a0 = *(const float4*)&A[(by + am) * N + kn + ak];
            a1 = *(const float4*)&A[(by + am + 32) * N + kn + ak];
            b0 = *(const float4*)&B[(kn + bk) * N + bx + bn];
            b1 = *(const float4*)&B[(kn + bk + 16) * N + bx + bn];
        }

#pragma unroll
        for (int kk = 0; kk < 32; kk++) {
            float4 a = *(const float4*)&As[kk][ty * 4];
            float4 b = *(const float4*)&Bs[kk][tx * 4];
            const float* ap = (const float*)&a;
            const float* bp = (const float*)&b;
#pragma unroll
            for (int i = 0; i < 4; i++)
#pragma unroll
                for (int j = 0; j < 4; j++)
                    acc[i][j] += ap[i] * bp[j];
        }
        __syncthreads();
    }

#pragma unroll
    for (int i = 0; i < 4; i++) {
        float4 r = make_float4(acc[i][0], acc[i][1], acc[i][2], acc[i][3]);
        *(float4*)&C[(by + ty * 4 + i) * N + bx + tx * 4] = r;
    }
}

// ---------------------------------------------------------------------------
// Kernel 3: sum KSPLIT s-partials + row softmax -> g_s. One block per row.
// ---------------------------------------------------------------------------
__global__ void __launch_bounds__(256) softmax_kernel()
{
    __shared__ float red[256];
    int row = blockIdx.x;
    size_t off = (size_t)row * N;
    int tid = threadIdx.x;

    float a = 0.0f, b = 0.0f;
#pragma unroll
    for (int z = 0; z < KSPLIT; z++) {
        a += g_sp[z][off + tid];
        b += g_sp[z][off + tid + 256];
    }

    red[tid] = fmaxf(a, b);
    __syncthreads();
#pragma unroll
    for (int o = 128; o > 0; o >>= 1) {
        if (tid < o) red[tid] = fmaxf(red[tid], red[tid + o]);
        __syncthreads();
    }
    float mx = red[0];
    __syncthreads();

    float ea = __expf(a - mx);
    float eb = __expf(b - mx);

    red[tid] = ea + eb;
    __syncthreads();
#pragma unroll
    for (int o = 128; o > 0; o >>= 1) {
        if (tid < o) red[tid] += red[tid + o];
        __syncthreads();
    }
    float inv = 1.0f / red[0];

    g_s[off + tid] = ea * inv;
    g_s[off + tid + 256] = eb * inv;
}

// ---------------------------------------------------------------------------
// Kernel 5: sum KSPLIT out-partials -> d_out (float4 vectorized).
// ---------------------------------------------------------------------------
__global__ void __launch_bounds__(256) reduce_out_kernel(float* __restrict__ out)
{
    int i = blockIdx.x * 256 + threadIdx.x;   // float4 index, 65536 total
    float4 r = ((const float4*)g_op[0])[i];
    float4 s1 = ((const float4*)g_op[1])[i];
    float4 s2 = ((const float4*)g_op[2])[i];
    float4 s3 = ((const float4*)g_op[3])[i];
    r.x += s1.x + s2.x + s3.x;
    r.y += s1.y + s2.y + s3.y;
    r.z += s1.z + s2.z + s3.z;
    r.w += s1.w + s2.w + s3.w;
    ((float4*)out)[i] = r;
}

// ---------------------------------------------------------------------------
extern "C" void kernel_launch(void* const* d_in, const int* in_sizes, int n_in,
                              void* d_out, int out_size)
{
    const float* xq = (const float*)d_in[0];
    const float* xk = (const float*)d_in[1];
    const float* xv = (const float*)d_in[2];
    const float* WQ = (const float*)d_in[3];
    const float* WK = (const float*)d_in[4];
    const float* WV = (const float*)d_in[5];
    float* out = (float*)d_out;

    int total_rows = 3 * N * N;
    proj_kernel<<<(total_rows + 7) / 8, 256>>>(xq, xk, xv, WQ, WK, WV);

    dim3 gg(N / 64, N / 64, KSPLIT);   // (8, 8, 4) = 256 blocks
    sgemm_kernel<<<gg, 256>>>(0);

    softmax_kernel<<<N, 256>>>();

    sgemm_kernel<<<gg, 256>>>(1);

    reduce_out_kernel<<<(N * N / 4) / 256, 256>>>(out);
}

// round 4
// speedup vs baseline: 1.3346x; 1.0180x over previous
#include <cuda_runtime.h>

#define N 512
#define D 256
#define KSPLIT 8

// Scratch (device globals — no allocation allowed)
__device__ float g_q[N * N];
__device__ float g_k[N * N];
__device__ float g_v[N * N];
__device__ float g_s[N * N];
__device__ float g_sp[KSPLIT][N * N];   // split-K partials of q@k
__device__ float g_op[KSPLIT][N * N];   // split-K partials of s@v

// ---------------------------------------------------------------------------
// Kernel 1: fused rank-1 projections. Streaming (read-once) loads via __ldcs.
// ---------------------------------------------------------------------------
__global__ void __launch_bounds__(256) proj_kernel(
    const float* __restrict__ xq, const float* __restrict__ xk,
    const float* __restrict__ xv, const float* __restrict__ WQ,
    const float* __restrict__ WK, const float* __restrict__ WV)
{
    __shared__ float sW[3][D];
    int tid = threadIdx.x;
    sW[0][tid] = WQ[tid];
    sW[1][tid] = WK[tid];
    sW[2][tid] = WV[tid];
    __syncthreads();

    int warp = tid >> 5;
    int lane = tid & 31;
    long long row = (long long)blockIdx.x * 8 + warp;
    if (row >= 3LL * N * N) return;

    int t = (int)(row / (N * N));
    int r = (int)(row % (N * N));

    const float* x = (t == 0) ? xq : (t == 1) ? xk : xv;
    const float4* xr = reinterpret_cast<const float4*>(x + (size_t)r * D);
    const float4* w4 = reinterpret_cast<const float4*>(sW[t]);

    // Issue both streaming loads up front (MLP=2/thread, evict-first policy)
    float4 a0 = __ldcs(&xr[lane]);
    float4 a1 = __ldcs(&xr[lane + 32]);
    float4 b0 = w4[lane];
    float4 b1 = w4[lane + 32];

    float acc = a0.x * b0.x + a0.y * b0.y + a0.z * b0.z + a0.w * b0.w
              + a1.x * b1.x + a1.y * b1.y + a1.z * b1.z + a1.w * b1.w;

#pragma unroll
    for (int o = 16; o > 0; o >>= 1)
        acc += __shfl_xor_sync(0xffffffffu, acc, o);

    if (lane == 0) {
        float* g = (t == 0) ? g_q : (t == 1) ? g_k : g_v;
        g[r] = acc;
    }
}

// ---------------------------------------------------------------------------
// Kernel 2/4: split-K SGEMM partials. BM=64, BN=64, BK=32; 4x4 microtile;
// grid (8,8,KSPLIT) = 512 blocks. K-slice per block = 64 (2 BK iterations).
// mode 0: A=g_q, B=g_k, C=g_sp[z];  mode 1: A=g_s, B=g_v, C=g_op[z]
// ---------------------------------------------------------------------------
__global__ void __launch_bounds__(256) sgemm_kernel(int mode)
{
    const float* __restrict__ A = (mode == 0) ? g_q : g_s;
    const float* __restrict__ B = (mode == 0) ? g_k : g_v;
    float* __restrict__ C = (mode == 0) ? g_sp[blockIdx.z] : g_op[blockIdx.z];

    __shared__ float As[32][68];   // [k][m], pad=4 keeps 16B align
    __shared__ float Bs[32][64];   // [k][n]

    const int bx = blockIdx.x * 64;
    const int by = blockIdx.y * 64;
    const int kbase = blockIdx.z * (N / KSPLIT);   // 64-wide K slice
    const int tid = threadIdx.x;
    const int tx = tid & 15;
    const int ty = tid >> 4;

    const int am = tid >> 3;
    const int ak = (tid & 7) * 4;
    const int bn = (tid & 15) * 4;
    const int bk = tid >> 4;

    float4 a0 = *(const float4*)&A[(by + am) * N + kbase + ak];
    float4 a1 = *(const float4*)&A[(by + am + 32) * N + kbase + ak];
    float4 b0 = *(const float4*)&B[(kbase + bk) * N + bx + bn];
    float4 b1 = *(const float4*)&B[(kbase + bk + 16) * N + bx + bn];

    float acc[4][4] = {};

    for (int k0 = 0; k0 < N / KSPLIT; k0 += 32) {
#pragma unroll
        for (int j = 0; j < 4; j++) {
            As[ak + j][am]      = ((const float*)&a0)[j];
            As[ak + j][am + 32] = ((const float*)&a1)[j];
        }
        *(float4*)&Bs[bk][bn]      = b0;
        *(float4*)&Bs[bk + 16][bn] = b1;
        __syncthreads();

        if (k0 + 32 < N / KSPLIT) {
            int kn = kbase + k0 + 32;
            a0 = *(const float4*)&A[(by + am) * N + kn + ak];
            a1 = *(const float4*)&A[(by + am + 32) * N + kn + ak];
            b0 = *(const float4*)&B[(kn + bk) * N + bx + bn];
            b1 = *(const float4*)&B[(kn + bk + 16) * N + bx + bn];
        }

#pragma unroll
        for (int kk = 0; kk < 32; kk++) {
            float4 a = *(const float4*)&As[kk][ty * 4];
            float4 b = *(const float4*)&Bs[kk][tx * 4];
            const float* ap = (const float*)&a;
            const float* bp = (const float*)&b;
#pragma unroll
            for (int i = 0; i < 4; i++)
#pragma unroll
                for (int j = 0; j < 4; j++)
                    acc[i][j] += ap[i] * bp[j];
        }
        __syncthreads();
    }

#pragma unroll
    for (int i = 0; i < 4; i++) {
        float4 r = make_float4(acc[i][0], acc[i][1], acc[i][2], acc[i][3]);
        *(float4*)&C[(by + ty * 4 + i) * N + bx + tx * 4] = r;
    }
}

// ---------------------------------------------------------------------------
// Kernel 3: sum KSPLIT s-partials + row softmax -> g_s. One block per row.
// ---------------------------------------------------------------------------
__global__ void __launch_bounds__(256) softmax_kernel()
{
    __shared__ float red[256];
    int row = blockIdx.x;
    size_t off = (size_t)row * N;
    int tid = threadIdx.x;

    float a = 0.0f, b = 0.0f;
#pragma unroll
    for (int z = 0; z < KSPLIT; z++) {
        a += g_sp[z][off + tid];
        b += g_sp[z][off + tid + 256];
    }

    red[tid] = fmaxf(a, b);
    __syncthreads();
#pragma unroll
    for (int o = 128; o > 0; o >>= 1) {
        if (tid < o) red[tid] = fmaxf(red[tid], red[tid + o]);
        __syncthreads();
    }
    float mx = red[0];
    __syncthreads();

    float ea = __expf(a - mx);
    float eb = __expf(b - mx);

    red[tid] = ea + eb;
    __syncthreads();
#pragma unroll
    for (int o = 128; o > 0; o >>= 1) {
        if (tid < o) red[tid] += red[tid + o];
        __syncthreads();
    }
    float inv = 1.0f / red[0];

    g_s[off + tid] = ea * inv;
    g_s[off + tid + 256] = eb * inv;
}

// ---------------------------------------------------------------------------
// Kernel 5: sum KSPLIT out-partials -> d_out (float4 vectorized).
// ---------------------------------------------------------------------------
__global__ void __launch_bounds__(256) reduce_out_kernel(float* __restrict__ out)
{
    int i = blockIdx.x * 256 + threadIdx.x;   // float4 index
    float4 r = ((const float4*)g_op[0])[i];
#pragma unroll
    for (int z = 1; z < KSPLIT; z++) {
        float4 s = ((const float4*)g_op[z])[i];
        r.x += s.x; r.y += s.y; r.z += s.z; r.w += s.w;
    }
    ((float4*)out)[i] = r;
}

// ---------------------------------------------------------------------------
extern "C" void kernel_launch(void* const* d_in, const int* in_sizes, int n_in,
                              void* d_out, int out_size)
{
    const float* xq = (const float*)d_in[0];
    const float* xk = (const float*)d_in[1];
    const float* xv = (const float*)d_in[2];
    const float* WQ = (const float*)d_in[3];
    const float* WK = (const float*)d_in[4];
    const float* WV = (const float*)d_in[5];
    float* out = (float*)d_out;

    int total_rows = 3 * N * N;
    proj_kernel<<<(total_rows + 7) / 8, 256>>>(xq, xk, xv, WQ, WK, WV);

    dim3 gg(N / 64, N / 64, KSPLIT);   // (8, 8, 8) = 512 blocks
    sgemm_kernel<<<gg, 256>>>(0);

    softmax_kernel<<<N, 256>>>();

    sgemm_kernel<<<gg, 256>>>(1);

    reduce_out_kernel<<<(N * N / 4) / 256, 256>>>(out);
}

// round 5
// speedup vs baseline: 1.3690x; 1.0258x over previous
#include <cuda_runtime.h>

#define N 512
#define D 256
#define KSPLIT 8

// Scratch (device globals — no allocation allowed)
__device__ float g_q[N * N];
__device__ float g_k[N * N];
__device__ float g_v[N * N];
__device__ float g_s[N * N];
__device__ float g_sp[KSPLIT][N * N];   // split-K partials of q@k
__device__ float g_op[KSPLIT][N * N];   // split-K partials of s@v

#define PROJ_BLOCKS 1184   // 148 SMs * 8 blocks (persistent single wave)

// ---------------------------------------------------------------------------
// Kernel 1: fused rank-1 projections, persistent grid-stride.
// One warp per row per iteration; weights loaded to smem once per block.
// ---------------------------------------------------------------------------
__global__ void __launch_bounds__(256) proj_kernel(
    const float* __restrict__ xq, const float* __restrict__ xk,
    const float* __restrict__ xv, const float* __restrict__ WQ,
    const float* __restrict__ WK, const float* __restrict__ WV)
{
    __shared__ float sW[3][D];
    int tid = threadIdx.x;
    sW[0][tid] = WQ[tid];
    sW[1][tid] = WK[tid];
    sW[2][tid] = WV[tid];
    __syncthreads();

    const int warp = tid >> 5;
    const int lane = tid & 31;
    const long long stride = (long long)PROJ_BLOCKS * 8;
    const long long total = 3LL * N * N;

    for (long long row = (long long)blockIdx.x * 8 + warp; row < total; row += stride) {
        int t = (int)(row >> 18);            // row / (512*512)
        int r = (int)(row & (N * N - 1));    // row % (512*512)

        const float* x = (t == 0) ? xq : (t == 1) ? xk : xv;
        const float4* xr = reinterpret_cast<const float4*>(x + (size_t)r * D);
        const float4* w4 = reinterpret_cast<const float4*>(sW[t]);

        float4 a0 = __ldcs(&xr[lane]);
        float4 a1 = __ldcs(&xr[lane + 32]);
        float4 b0 = w4[lane];
        float4 b1 = w4[lane + 32];

        float acc = a0.x * b0.x + a0.y * b0.y + a0.z * b0.z + a0.w * b0.w
                  + a1.x * b1.x + a1.y * b1.y + a1.z * b1.z + a1.w * b1.w;

#pragma unroll
        for (int o = 16; o > 0; o >>= 1)
            acc += __shfl_xor_sync(0xffffffffu, acc, o);

        if (lane == 0) {
            float* g = (t == 0) ? g_q : (t == 1) ? g_k : g_v;
            g[r] = acc;
        }
    }
}

// ---------------------------------------------------------------------------
// Kernel 2/4: split-K SGEMM partials. BM=128, BN=64, BK=32; 8x4 microtile;
// 256 threads; grid (8,4,KSPLIT)=256 blocks (single wave). K-slice = 64.
// mode 0: A=g_q, B=g_k, C=g_sp[z];  mode 1: A=g_s, B=g_v, C=g_op[z]
// ---------------------------------------------------------------------------
__global__ void __launch_bounds__(256) sgemm_kernel(int mode)
{
    const float* __restrict__ A = (mode == 0) ? g_q : g_s;
    const float* __restrict__ B = (mode == 0) ? g_k : g_v;
    float* __restrict__ C = (mode == 0) ? g_sp[blockIdx.z] : g_op[blockIdx.z];

    __shared__ float As[32][136];   // [k][m], pad 8 keeps 16B alignment
    __shared__ float Bs[32][64];    // [k][n]

    const int bx = blockIdx.x * 64;               // n offset
    const int by = blockIdx.y * 128;              // m offset
    const int kbase = blockIdx.z * (N / KSPLIT);  // 64-wide K slice
    const int tid = threadIdx.x;
    const int tx = tid & 15;                      // n micro (16*4 = 64)
    const int ty = tid >> 4;                      // m micro (16*8 = 128)

    // Global load assignments
    const int am = tid >> 1;                      // A row 0..127 (2 thr/row)
    const int ah = (tid & 1) * 16;                // A k half offset
    const int bn = (tid & 15) * 4;                // B n, float4
    const int bk = tid >> 4;                      // B k; +16 for 2nd

    // Prefetch first tile
    float4 aR[4];
#pragma unroll
    for (int j = 0; j < 4; j++)
        aR[j] = *(const float4*)&A[(by + am) * N + kbase + ah + j * 4];
    float4 b0 = *(const float4*)&B[(kbase + bk) * N + bx + bn];
    float4 b1 = *(const float4*)&B[(kbase + bk + 16) * N + bx + bn];

    float acc[8][4] = {};

    for (int k0 = 0; k0 < N / KSPLIT; k0 += 32) {
        // Commit prefetched tile (A transposed to [k][m])
#pragma unroll
        for (int j = 0; j < 4; j++) {
            As[ah + j * 4 + 0][am] = aR[j].x;
            As[ah + j * 4 + 1][am] = aR[j].y;
            As[ah + j * 4 + 2][am] = aR[j].z;
            As[ah + j * 4 + 3][am] = aR[j].w;
        }
        *(float4*)&Bs[bk][bn]      = b0;
        *(float4*)&Bs[bk + 16][bn] = b1;
        __syncthreads();

        // Prefetch next tile
        if (k0 + 32 < N / KSPLIT) {
            int kn = kbase + k0 + 32;
#pragma unroll
            for (int j = 0; j < 4; j++)
                aR[j] = *(const float4*)&A[(by + am) * N + kn + ah + j * 4];
            b0 = *(const float4*)&B[(kn + bk) * N + bx + bn];
            b1 = *(const float4*)&B[(kn + bk + 16) * N + bx + bn];
        }

#pragma unroll
        for (int kk = 0; kk < 32; kk++) {
            float4 a0 = *(const float4*)&As[kk][ty * 8];
            float4 a1 = *(const float4*)&As[kk][ty * 8 + 4];
            float4 b  = *(const float4*)&Bs[kk][tx * 4];
            const float* ap0 = (const float*)&a0;
            const float* ap1 = (const float*)&a1;
            const float* bp  = (const float*)&b;
#pragma unroll
            for (int i = 0; i < 4; i++)
#pragma unroll
                for (int j = 0; j < 4; j++) {
                    acc[i][j]     += ap0[i] * bp[j];
                    acc[i + 4][j] += ap1[i] * bp[j];
                }
        }
        __syncthreads();
    }

#pragma unroll
    for (int i = 0; i < 8; i++) {
        float4 r = make_float4(acc[i][0], acc[i][1], acc[i][2], acc[i][3]);
        *(float4*)&C[(by + ty * 8 + i) * N + bx + tx * 4] = r;
    }
}

// ---------------------------------------------------------------------------
// Kernel 3: sum KSPLIT s-partials + row softmax -> g_s. One block per row.
// ---------------------------------------------------------------------------
__global__ void __launch_bounds__(256) softmax_kernel()
{
    __shared__ float red[256];
    int row = blockIdx.x;
    size_t off = (size_t)row * N;
    int tid = threadIdx.x;

    float a = 0.0f, b = 0.0f;
#pragma unroll
    for (int z = 0; z < KSPLIT; z++) {
        a += g_sp[z][off + tid];
        b += g_sp[z][off + tid + 256];
    }

    red[tid] = fmaxf(a, b);
    __syncthreads();
#pragma unroll
    for (int o = 128; o > 0; o >>= 1) {
        if (tid < o) red[tid] = fmaxf(red[tid], red[tid + o]);
        __syncthreads();
    }
    float mx = red[0];
    __syncthreads();

    float ea = __expf(a - mx);
    float eb = __expf(b - mx);

    red[tid] = ea + eb;
    __syncthreads();
#pragma unroll
    for (int o = 128; o > 0; o >>= 1) {
        if (tid < o) red[tid] += red[tid + o];
        __syncthreads();
    }
    float inv = 1.0f / red[0];

    g_s[off + tid] = ea * inv;
    g_s[off + tid + 256] = eb * inv;
}

// ---------------------------------------------------------------------------
// Kernel 5: sum KSPLIT out-partials -> d_out (float4 vectorized).
// ---------------------------------------------------------------------------
__global__ void __launch_bounds__(256) reduce_out_kernel(float* __restrict__ out)
{
    int i = blockIdx.x * 256 + threadIdx.x;   // float4 index
    float4 r = ((const float4*)g_op[0])[i];
#pragma unroll
    for (int z = 1; z < KSPLIT; z++) {
        float4 s = ((const float4*)g_op[z])[i];
        r.x += s.x; r.y += s.y; r.z += s.z; r.w += s.w;
    }
    ((float4*)out)[i] = r;
}

// ---------------------------------------------------------------------------
extern "C" void kernel_launch(void* const* d_in, const int* in_sizes, int n_in,
                              void* d_out, int out_size)
{
    const float* xq = (const float*)d_in[0];
    const float* xk = (const float*)d_in[1];
    const float* xv = (const float*)d_in[2];
    const float* WQ = (const float*)d_in[3];
    const float* WK = (const float*)d_in[4];
    const float* WV = (const float*)d_in[5];
    float* out = (float*)d_out;

    proj_kernel<<<PROJ_BLOCKS, 256>>>(xq, xk, xv, WQ, WK, WV);

    dim3 gg(N / 64, N / 128, KSPLIT);   // (8, 4, 8) = 256 blocks
    sgemm_kernel<<<gg, 256>>>(0);

    softmax_kernel<<<N, 256>>>();

    sgemm_kernel<<<gg, 256>>>(1);

    reduce_out_kernel<<<(N * N / 4) / 256, 256>>>(out);
}